// round 3
// baseline (speedup 1.0000x reference)
#include <cuda_runtime.h>
#include <cuda_bf16.h>
#include <math.h>

#define E_ 7
#define K_ 2
#define CAP_ 3072
#define D_ 1024
#define H_ 4096
#define T_ 8192
#define TK_ (T_ * K_)

// ---------------- scratch (device globals; no allocation allowed) ----------------
__device__ float g_buf[(size_t)E_ * CAP_ * D_];   // dispatched tokens  [E,CAP,D]   88 MB
__device__ float g_h  [(size_t)E_ * CAP_ * H_];   // hidden activations [E,CAP,H]  352 MB
__device__ float g_y  [(size_t)E_ * CAP_ * D_];   // expert outputs     [E,CAP,D]   88 MB
__device__ int   g_expert[TK_];
__device__ int   g_slot[TK_];
__device__ float g_w[TK_];
__device__ int   g_count[E_];

// ---------------- router: logits, top-2, weights, slot assignment ----------------
__global__ void zero_counts_kernel() {
    if (threadIdx.x < E_) g_count[threadIdx.x] = 0;
}

__global__ void router_kernel(const float* __restrict__ x,
                              const float* __restrict__ Wg) {
    int warp = (blockIdx.x * blockDim.x + threadIdx.x) >> 5;
    int lane = threadIdx.x & 31;
    if (warp >= T_) return;
    const float* xr = x + (size_t)warp * D_;
    float acc[E_];
#pragma unroll
    for (int e = 0; e < E_; e++) acc[e] = 0.f;
    for (int d = lane; d < D_; d += 32) {
        float xv = xr[d];
        const float* wr = Wg + (size_t)d * E_;
#pragma unroll
        for (int e = 0; e < E_; e++) acc[e] += xv * wr[e];
    }
#pragma unroll
    for (int e = 0; e < E_; e++)
#pragma unroll
        for (int o = 16; o; o >>= 1) acc[e] += __shfl_xor_sync(0xffffffffu, acc[e], o);

    if (lane == 0) {
        // top-1 (first occurrence on ties, matching jax top_k)
        int i1 = 0; float l1 = acc[0];
#pragma unroll
        for (int e = 1; e < E_; e++) if (acc[e] > l1) { l1 = acc[e]; i1 = e; }
        // top-2
        int i2 = -1; float l2 = -3.4e38f;
#pragma unroll
        for (int e = 0; e < E_; e++) if (e != i1 && acc[e] > l2) { l2 = acc[e]; i2 = e; }
        // renormalized softmax over the two kept logits
        float w2 = 1.f / (1.f + expf(l1 - l2));
        float w1 = 1.f - w2;
        int s1 = atomicAdd(&g_count[i1], 1);
        int s2 = atomicAdd(&g_count[i2], 1);
        int a = 2 * warp;
        g_expert[a] = i1; g_slot[a] = s1; g_w[a] = w1;
        g_expert[a + 1] = i2; g_slot[a + 1] = s2; g_w[a + 1] = w2;
    }
}

// ---------------- dispatch: copy x rows into [E,CAP,D] buffer ----------------
__global__ void scatter_kernel(const float* __restrict__ x) {
    int a = blockIdx.x;                // assignment id [0, T*K)
    int s = g_slot[a];
    if (s >= CAP_) return;             // overflow -> dropped
    int e = g_expert[a];
    int t = a >> 1;
    const float4* src = (const float4*)(x + (size_t)t * D_);
    float4* dst = (float4*)(g_buf + ((size_t)e * CAP_ + s) * D_);
    dst[threadIdx.x] = src[threadIdx.x];   // 256 threads * float4 = 1024 floats
}

// ---------------- grouped SGEMM: C[e] = A[e] @ B[e], optional fused GELU ----------------
// BM=BN=128, BK=16, 256 threads, 8x8 micro-tile. All dims divide the tiles exactly.
__device__ __forceinline__ float gelu_tanh(float v) {
    float c = v + 0.044715f * v * v * v;
    return 0.5f * v * (1.f + tanhf(0.7978845608028654f * c));
}

template <bool GELU>
__global__ __launch_bounds__(256, 2)
void sgemm_grouped(const float* __restrict__ Abase, const float* __restrict__ Bbase,
                   float* __restrict__ Cbase,
                   int N, int K, size_t strideAe, size_t strideBe, size_t strideCe) {
    __shared__ float As[16][128];
    __shared__ float Bs[16][128];

    int e = blockIdx.z;
    const float* A = Abase + (size_t)e * strideAe + (size_t)blockIdx.y * 128 * K;
    const float* B = Bbase + (size_t)e * strideBe + (size_t)blockIdx.x * 128;
    float* C = Cbase + (size_t)e * strideCe + (size_t)blockIdx.y * 128 * N + (size_t)blockIdx.x * 128;

    int tid = threadIdx.x;
    int tx = tid & 15;          // 0..15  -> column group (8 cols)
    int ty = tid >> 4;          // 0..15  -> row group (8 rows)

    float acc[8][8];
#pragma unroll
    for (int i = 0; i < 8; i++)
#pragma unroll
        for (int j = 0; j < 8; j++) acc[i][j] = 0.f;

    for (int k0 = 0; k0 < K; k0 += 16) {
        // load A tile (128 x 16) transposed into As[k][m]
#pragma unroll
        for (int it = 0; it < 2; it++) {
            int id = tid + it * 256;           // 0..511
            int m = id >> 2, k4 = id & 3;
            float4 v = *(const float4*)(A + (size_t)m * K + k0 + k4 * 4);
            As[k4 * 4 + 0][m] = v.x;
            As[k4 * 4 + 1][m] = v.y;
            As[k4 * 4 + 2][m] = v.z;
            As[k4 * 4 + 3][m] = v.w;
        }
        // load B tile (16 x 128)
#pragma unroll
        for (int it = 0; it < 2; it++) {
            int id = tid + it * 256;
            int k = id >> 5, n4 = id & 31;
            *(float4*)(&Bs[k][n4 * 4]) =
                *(const float4*)(B + (size_t)(k0 + k) * N + n4 * 4);
        }
        __syncthreads();

#pragma unroll
        for (int k = 0; k < 16; k++) {
            float a[8], b[8];
            *(float4*)(a)     = *(float4*)(&As[k][ty * 8]);
            *(float4*)(a + 4) = *(float4*)(&As[k][ty * 8 + 4]);
            *(float4*)(b)     = *(float4*)(&Bs[k][tx * 8]);
            *(float4*)(b + 4) = *(float4*)(&Bs[k][tx * 8 + 4]);
#pragma unroll
            for (int i = 0; i < 8; i++)
#pragma unroll
                for (int j = 0; j < 8; j++) acc[i][j] = fmaf(a[i], b[j], acc[i][j]);
        }
        __syncthreads();
    }

    // epilogue
#pragma unroll
    for (int i = 0; i < 8; i++) {
        int m = ty * 8 + i;
#pragma unroll
        for (int jj = 0; jj < 2; jj++) {
            float4 v;
            v.x = acc[i][jj * 4 + 0];
            v.y = acc[i][jj * 4 + 1];
            v.z = acc[i][jj * 4 + 2];
            v.w = acc[i][jj * 4 + 3];
            if (GELU) {
                v.x = gelu_tanh(v.x); v.y = gelu_tanh(v.y);
                v.z = gelu_tanh(v.z); v.w = gelu_tanh(v.w);
            }
            *(float4*)(C + (size_t)m * N + tx * 8 + jj * 4) = v;
        }
    }
}

// ---------------- combine: out[t] = sum_k w * y[e,slot] ----------------
__global__ void combine_kernel(float* __restrict__ out) {
    int t = blockIdx.x;
    float4 acc = make_float4(0.f, 0.f, 0.f, 0.f);
#pragma unroll
    for (int k = 0; k < K_; k++) {
        int a = K_ * t + k;
        int s = g_slot[a];
        if (s < CAP_) {
            float ww = g_w[a];
            int e = g_expert[a];
            float4 v = ((const float4*)(g_y + ((size_t)e * CAP_ + s) * D_))[threadIdx.x];
            acc.x += ww * v.x; acc.y += ww * v.y;
            acc.z += ww * v.z; acc.w += ww * v.w;
        }
    }
    ((float4*)(out + (size_t)t * D_))[threadIdx.x] = acc;
}

// ---------------- launch ----------------
extern "C" void kernel_launch(void* const* d_in, const int* in_sizes, int n_in,
                              void* d_out, int out_size) {
    const float* x  = (const float*)d_in[0];   // [T, D]
    const float* Wg = (const float*)d_in[1];   // [D, E]
    const float* W1 = (const float*)d_in[2];   // [E, D, H]
    const float* W2 = (const float*)d_in[3];   // [E, H, D]
    float* out = (float*)d_out;                // [T, D]

    void *p_buf, *p_h, *p_y;
    cudaGetSymbolAddress(&p_buf, g_buf);
    cudaGetSymbolAddress(&p_h, g_h);
    cudaGetSymbolAddress(&p_y, g_y);

    zero_counts_kernel<<<1, 32>>>();
    router_kernel<<<T_ / 8, 256>>>(x, Wg);          // 8 warps/block, 1 token/warp
    scatter_kernel<<<TK_, 256>>>(x);

    // GEMM1: h = gelu(buf @ W1)   [CAP,1024] x [1024,4096]
    {
        dim3 grid(H_ / 128, CAP_ / 128, E_);
        sgemm_grouped<true><<<grid, 256>>>(
            (const float*)p_buf, W1, (float*)p_h,
            H_, D_,
            (size_t)CAP_ * D_, (size_t)D_ * H_, (size_t)CAP_ * H_);
    }
    // GEMM2: y = h @ W2   [CAP,4096] x [4096,1024]
    {
        dim3 grid(D_ / 128, CAP_ / 128, E_);
        sgemm_grouped<false><<<grid, 256>>>(
            (const float*)p_h, W2, (float*)p_y,
            D_, H_,
            (size_t)CAP_ * H_, (size_t)H_ * D_, (size_t)CAP_ * D_);
    }
    combine_kernel<<<T_, 256>>>(out);
}

// round 5
// speedup vs baseline: 3.6772x; 3.6772x over previous
#include <cuda_runtime.h>
#include <cuda_bf16.h>
#include <math.h>

#define E_ 7
#define K_ 2
#define CAP_ 3072
#define D_ 1024
#define H_ 4096
#define T_ 8192
#define TK_ (T_ * K_)

// ---------------- scratch (device globals; no allocation allowed) ----------------
__device__ float g_buf[(size_t)E_ * CAP_ * D_];   // dispatched tokens  [E,CAP,D]
__device__ float g_h  [(size_t)E_ * CAP_ * H_];   // hidden activations [E,CAP,H]
__device__ float g_y  [(size_t)E_ * CAP_ * D_];   // expert outputs     [E,CAP,D]
__device__ int   g_expert[TK_];
__device__ int   g_slot[TK_];
__device__ float g_w[TK_];
__device__ int   g_count[E_];

// ---------------- router ----------------
__global__ void zero_counts_kernel() {
    if (threadIdx.x < E_) g_count[threadIdx.x] = 0;
}

__global__ void router_kernel(const float* __restrict__ x,
                              const float* __restrict__ Wg) {
    int warp = (blockIdx.x * blockDim.x + threadIdx.x) >> 5;
    int lane = threadIdx.x & 31;
    if (warp >= T_) return;
    const float* xr = x + (size_t)warp * D_;
    float acc[E_];
#pragma unroll
    for (int e = 0; e < E_; e++) acc[e] = 0.f;
    for (int d = lane; d < D_; d += 32) {
        float xv = xr[d];
        const float* wr = Wg + (size_t)d * E_;
#pragma unroll
        for (int e = 0; e < E_; e++) acc[e] += xv * wr[e];
    }
#pragma unroll
    for (int e = 0; e < E_; e++)
#pragma unroll
        for (int o = 16; o; o >>= 1) acc[e] += __shfl_xor_sync(0xffffffffu, acc[e], o);

    if (lane == 0) {
        int i1 = 0; float l1 = acc[0];
#pragma unroll
        for (int e = 1; e < E_; e++) if (acc[e] > l1) { l1 = acc[e]; i1 = e; }
        int i2 = -1; float l2 = -3.4e38f;
#pragma unroll
        for (int e = 0; e < E_; e++) if (e != i1 && acc[e] > l2) { l2 = acc[e]; i2 = e; }
        float w2 = 1.f / (1.f + expf(l1 - l2));
        float w1 = 1.f - w2;
        int s1 = atomicAdd(&g_count[i1], 1);
        int s2 = atomicAdd(&g_count[i2], 1);
        int a = 2 * warp;
        g_expert[a] = i1; g_slot[a] = s1; g_w[a] = w1;
        g_expert[a + 1] = i2; g_slot[a + 1] = s2; g_w[a + 1] = w2;
    }
}

// ---------------- dispatch ----------------
__global__ void scatter_kernel(const float* __restrict__ x) {
    int a = blockIdx.x;
    int s = g_slot[a];
    if (s >= CAP_) return;
    int e = g_expert[a];
    int t = a >> 1;
    const float4* src = (const float4*)(x + (size_t)t * D_);
    float4* dst = (float4*)(g_buf + ((size_t)e * CAP_ + s) * D_);
    dst[threadIdx.x] = src[threadIdx.x];
}

// ---------------- TF32 tensor-core grouped GEMM ----------------
// BM=BN=128, BK=32, 256 threads = 8 warps (2x4), warp tile 64x32,
// mma m16n8k8 tf32, fp32 accumulate. Early-exit on per-expert row count.

__device__ __forceinline__ float to_tf32(float x) {
    asm("cvt.rna.tf32.f32 %0, %0;" : "+f"(x));
    return x;
}

__device__ __forceinline__ float gelu_tanh(float v) {
    float c = v + 0.044715f * v * v * v;
    return 0.5f * v * (1.f + tanhf(0.7978845608028654f * c));
}

#define AS_STRIDE 36   // BK(32) + 4 pad -> conflict-free A-frag LDS
#define BS_STRIDE 132  // BN(128) + 4 pad -> conflict-free B-frag LDS

template <bool GELU>
__global__ __launch_bounds__(256, 2)
void tf32_gemm_grouped(const float* __restrict__ Abase, const float* __restrict__ Bbase,
                       float* __restrict__ Cbase,
                       int N, int Kdim, size_t sAe, size_t sBe, size_t sCe) {
    int e = blockIdx.z;
    int mlim = min(g_count[e], CAP_);
    if ((int)blockIdx.y * 128 >= mlim) return;   // skip unpopulated capacity tiles

    __shared__ float As[128][AS_STRIDE];
    __shared__ float Bs[32][BS_STRIDE];

    const float* A = Abase + (size_t)e * sAe + (size_t)blockIdx.y * 128 * Kdim;
    const float* B = Bbase + (size_t)e * sBe + (size_t)blockIdx.x * 128;
    float* C = Cbase + (size_t)e * sCe + (size_t)blockIdx.y * 128 * N + (size_t)blockIdx.x * 128;

    const int tid = threadIdx.x;
    const int lane = tid & 31;
    const int warp = tid >> 5;
    const int wm = (warp >> 2) * 64;   // warp m base (0 or 64)
    const int wn = (warp & 3) * 32;    // warp n base (0,32,64,96)
    const int r = lane >> 2;           // 0..7
    const int c = lane & 3;            // 0..3

    float acc[4][4][4];
#pragma unroll
    for (int mi = 0; mi < 4; mi++)
#pragma unroll
        for (int ni = 0; ni < 4; ni++)
#pragma unroll
            for (int q = 0; q < 4; q++) acc[mi][ni][q] = 0.f;

    for (int k0 = 0; k0 < Kdim; k0 += 32) {
        // stage A tile: 128 x 32, coalesced along k, As[m][k]
#pragma unroll
        for (int it = 0; it < 4; it++) {
            int id = tid + it * 256;           // 0..1023
            int m = id >> 3, kq = id & 7;
            float4 v = *(const float4*)(A + (size_t)m * Kdim + k0 + kq * 4);
            v.x = to_tf32(v.x); v.y = to_tf32(v.y);
            v.z = to_tf32(v.z); v.w = to_tf32(v.w);
            *(float4*)(&As[m][kq * 4]) = v;
        }
        // stage B tile: 32 x 128, coalesced along n, Bs[k][n]
#pragma unroll
        for (int it = 0; it < 4; it++) {
            int id = tid + it * 256;
            int kk = id >> 5, n4 = id & 31;
            float4 v = *(const float4*)(B + (size_t)(k0 + kk) * N + n4 * 4);
            v.x = to_tf32(v.x); v.y = to_tf32(v.y);
            v.z = to_tf32(v.z); v.w = to_tf32(v.w);
            *(float4*)(&Bs[kk][n4 * 4]) = v;
        }
        __syncthreads();

#pragma unroll
        for (int ks = 0; ks < 4; ks++) {
            const int kb = ks * 8;
            float a[4][4];
#pragma unroll
            for (int mi = 0; mi < 4; mi++) {
                int mb = wm + mi * 16;
                a[mi][0] = As[mb + r][kb + c];
                a[mi][1] = As[mb + r + 8][kb + c];
                a[mi][2] = As[mb + r][kb + c + 4];
                a[mi][3] = As[mb + r + 8][kb + c + 4];
            }
            float b[4][2];
#pragma unroll
            for (int ni = 0; ni < 4; ni++) {
                int nb = wn + ni * 8;
                b[ni][0] = Bs[kb + c][nb + r];
                b[ni][1] = Bs[kb + c + 4][nb + r];
            }
#pragma unroll
            for (int mi = 0; mi < 4; mi++)
#pragma unroll
                for (int ni = 0; ni < 4; ni++) {
                    asm volatile(
                        "mma.sync.aligned.m16n8k8.row.col.f32.tf32.tf32.f32 "
                        "{%0,%1,%2,%3}, {%4,%5,%6,%7}, {%8,%9}, {%0,%1,%2,%3};\n"
                        : "+f"(acc[mi][ni][0]), "+f"(acc[mi][ni][1]),
                          "+f"(acc[mi][ni][2]), "+f"(acc[mi][ni][3])
                        : "r"(__float_as_uint(a[mi][0])), "r"(__float_as_uint(a[mi][1])),
                          "r"(__float_as_uint(a[mi][2])), "r"(__float_as_uint(a[mi][3])),
                          "r"(__float_as_uint(b[ni][0])), "r"(__float_as_uint(b[ni][1])));
                }
        }
        __syncthreads();
    }

    // epilogue: c0,c1 at (row, 2c..2c+1); c2,c3 at (row+8, ...)
#pragma unroll
    for (int mi = 0; mi < 4; mi++) {
        int row0 = wm + mi * 16 + r;
#pragma unroll
        for (int ni = 0; ni < 4; ni++) {
            int col = wn + ni * 8 + 2 * c;
            float2 v0 = make_float2(acc[mi][ni][0], acc[mi][ni][1]);
            float2 v1 = make_float2(acc[mi][ni][2], acc[mi][ni][3]);
            if (GELU) {
                v0.x = gelu_tanh(v0.x); v0.y = gelu_tanh(v0.y);
                v1.x = gelu_tanh(v1.x); v1.y = gelu_tanh(v1.y);
            }
            *(float2*)(C + (size_t)row0 * N + col) = v0;
            *(float2*)(C + (size_t)(row0 + 8) * N + col) = v1;
        }
    }
}

// ---------------- combine ----------------
__global__ void combine_kernel(float* __restrict__ out) {
    int t = blockIdx.x;
    float4 acc = make_float4(0.f, 0.f, 0.f, 0.f);
#pragma unroll
    for (int k = 0; k < K_; k++) {
        int a = K_ * t + k;
        int s = g_slot[a];
        if (s < CAP_) {
            float ww = g_w[a];
            int e = g_expert[a];
            float4 v = ((const float4*)(g_y + ((size_t)e * CAP_ + s) * D_))[threadIdx.x];
            acc.x += ww * v.x; acc.y += ww * v.y;
            acc.z += ww * v.z; acc.w += ww * v.w;
        }
    }
    ((float4*)(out + (size_t)t * D_))[threadIdx.x] = acc;
}

// ---------------- launch ----------------
extern "C" void kernel_launch(void* const* d_in, const int* in_sizes, int n_in,
                              void* d_out, int out_size) {
    const float* x  = (const float*)d_in[0];   // [T, D]
    const float* Wg = (const float*)d_in[1];   // [D, E]
    const float* W1 = (const float*)d_in[2];   // [E, D, H]
    const float* W2 = (const float*)d_in[3];   // [E, H, D]
    float* out = (float*)d_out;                // [T, D]

    void *p_buf, *p_h, *p_y;
    cudaGetSymbolAddress(&p_buf, g_buf);
    cudaGetSymbolAddress(&p_h, g_h);
    cudaGetSymbolAddress(&p_y, g_y);

    zero_counts_kernel<<<1, 32>>>();
    router_kernel<<<T_ / 8, 256>>>(x, Wg);
    scatter_kernel<<<TK_, 256>>>(x);

    // GEMM1: h = gelu(buf @ W1)   [CAP,1024] x [1024,4096]
    {
        dim3 grid(H_ / 128, CAP_ / 128, E_);
        tf32_gemm_grouped<true><<<grid, 256>>>(
            (const float*)p_buf, W1, (float*)p_h,
            H_, D_,
            (size_t)CAP_ * D_, (size_t)D_ * H_, (size_t)CAP_ * H_);
    }
    // GEMM2: y = h @ W2   [CAP,4096] x [4096,1024]
    {
        dim3 grid(D_ / 128, CAP_ / 128, E_);
        tf32_gemm_grouped<false><<<grid, 256>>>(
            (const float*)p_h, W2, (float*)p_y,
            D_, H_,
            (size_t)CAP_ * H_, (size_t)H_ * D_, (size_t)CAP_ * D_);
    }
    combine_kernel<<<T_, 256>>>(out);
}

// round 14
// speedup vs baseline: 8.7529x; 2.3803x over previous
#include <cuda.h>
#include <cuda_runtime.h>
#include <cuda_bf16.h>
#include <math.h>
#include <stdint.h>

#define E_ 7
#define K_ 2
#define CAP_ 3072
#define D_ 1024
#define H_ 4096
#define T_ 8192
#define TK_ (T_ * K_)

// ---------------- scratch (device globals; no allocation allowed) ----------------
__device__ float g_buf[(size_t)E_ * CAP_ * D_];   // dispatched tokens  [E,CAP,D] (tf32-rounded)
__device__ float g_h  [(size_t)E_ * CAP_ * H_];   // hidden activations [E,CAP,H] (tf32-rounded)
__device__ float g_y  [(size_t)E_ * CAP_ * D_];   // expert outputs     [E,CAP,D]
__device__ float g_w1t[(size_t)E_ * H_ * D_];     // W1^T  [E,H,D] (tf32-rounded)
__device__ float g_w2t[(size_t)E_ * D_ * H_];     // W2^T  [E,D,H] (tf32-rounded)
__device__ int   g_expert[TK_];
__device__ int   g_slot[TK_];
__device__ float g_w[TK_];
__device__ int   g_count[E_];

// ---------------- common helpers ----------------
__device__ __forceinline__ float to_tf32(float x) {
    asm("cvt.rna.tf32.f32 %0, %0;" : "+f"(x));
    return x;
}
__device__ __forceinline__ float gelu_tanh(float v) {
    float c = v + 0.044715f * v * v * v;
    return 0.5f * v * (1.f + tanhf(0.7978845608028654f * c));
}
__device__ __forceinline__ uint32_t smem_u32(const void* p) {
    uint32_t a;
    asm("{ .reg .u64 t; cvta.to.shared.u64 t, %1; cvt.u32.u64 %0, t; }" : "=r"(a) : "l"(p));
    return a;
}
__device__ __forceinline__ uint32_t elect_one() {
    uint32_t p;
    asm volatile("{ .reg .pred p; elect.sync _|p, 0xFFFFFFFF; selp.b32 %0,1,0,p; }" : "=r"(p));
    return p;
}

#define MBARRIER_INIT(addr, cnt) \
    asm volatile("mbarrier.init.shared.b64 [%0], %1;" :: "r"(addr), "r"(cnt) : "memory")
#define MBARRIER_EXPECT_TX(addr, bytes) \
    asm volatile("mbarrier.arrive.expect_tx.shared.b64 _, [%0], %1;" :: "r"(addr), "r"(bytes) : "memory")

#define MBARRIER_WAIT_PARITY(mbar_, par_) do { \
    uint32_t _m = (mbar_), _p = (par_), _d; \
    asm volatile("{\n\t.reg .pred p;\n\t" \
        "mbarrier.try_wait.parity.acquire.cta.shared::cta.b64 p, [%1], %2;\n\t" \
        "selp.b32 %0, 1, 0, p;\n\t}" : "=r"(_d) : "r"(_m), "r"(_p) : "memory"); \
    if (!_d) { \
        asm volatile("{\n\t.reg .pred P1;\n\t" \
            "WL_%=:\n\t" \
            "mbarrier.try_wait.parity.acquire.cta.shared::cta.b64 P1, [%0], %1, 0x989680;\n\t" \
            "@P1 bra.uni WD_%=;\n\t" \
            "bra.uni WL_%=;\n\t" \
            "WD_%=:\n\t}" :: "r"(_m), "r"(_p) : "memory"); \
    } \
} while (0)

#define MBARRIER_WAIT_PARITY_RELAXED(mbar_, par_) do { \
    uint32_t _m = (mbar_), _p = (par_), _d; \
    asm volatile("{\n\t.reg .pred p;\n\t" \
        "mbarrier.try_wait.parity.relaxed.cta.shared::cta.b64 p, [%1], %2, 0x989680;\n\t" \
        "selp.b32 %0, 1, 0, p;\n\t}" : "=r"(_d) : "r"(_m), "r"(_p) : "memory"); \
    if (!_d) { \
        asm volatile("{\n\t.reg .pred P1;\n\t" \
            "WL_%=:\n\t" \
            "mbarrier.try_wait.parity.relaxed.cta.shared::cta.b64 P1, [%0], %1, 0x989680;\n\t" \
            "@P1 bra.uni WD_%=;\n\t" \
            "bra.uni WL_%=;\n\t" \
            "WD_%=:\n\t}" :: "r"(_m), "r"(_p) : "memory"); \
    } \
} while (0)

// ---------------- router ----------------
__global__ void zero_counts_kernel() {
    if (threadIdx.x < E_) g_count[threadIdx.x] = 0;
}

__global__ void router_kernel(const float* __restrict__ x,
                              const float* __restrict__ Wg) {
    int warp = (blockIdx.x * blockDim.x + threadIdx.x) >> 5;
    int lane = threadIdx.x & 31;
    if (warp >= T_) return;
    const float* xr = x + (size_t)warp * D_;
    float acc[E_];
#pragma unroll
    for (int e = 0; e < E_; e++) acc[e] = 0.f;
    for (int d = lane; d < D_; d += 32) {
        float xv = xr[d];
        const float* wr = Wg + (size_t)d * E_;
#pragma unroll
        for (int e = 0; e < E_; e++) acc[e] += xv * wr[e];
    }
#pragma unroll
    for (int e = 0; e < E_; e++)
#pragma unroll
        for (int o = 16; o; o >>= 1) acc[e] += __shfl_xor_sync(0xffffffffu, acc[e], o);

    if (lane == 0) {
        int i1 = 0; float l1 = acc[0];
#pragma unroll
        for (int e = 1; e < E_; e++) if (acc[e] > l1) { l1 = acc[e]; i1 = e; }
        int i2 = -1; float l2 = -3.4e38f;
#pragma unroll
        for (int e = 0; e < E_; e++) if (e != i1 && acc[e] > l2) { l2 = acc[e]; i2 = e; }
        float w2 = 1.f / (1.f + expf(l1 - l2));
        float w1 = 1.f - w2;
        int s1 = atomicAdd(&g_count[i1], 1);
        int s2 = atomicAdd(&g_count[i2], 1);
        int a = 2 * warp;
        g_expert[a] = i1; g_slot[a] = s1; g_w[a] = w1;
        g_expert[a + 1] = i2; g_slot[a + 1] = s2; g_w[a + 1] = w2;
    }
}

// ---------------- dispatch (tf32-rounds x on the way in) ----------------
__global__ void scatter_kernel(const float* __restrict__ x) {
    int a = blockIdx.x;
    int s = g_slot[a];
    if (s >= CAP_) return;
    int e = g_expert[a];
    int t = a >> 1;
    const float4* src = (const float4*)(x + (size_t)t * D_);
    float4* dst = (float4*)(g_buf + ((size_t)e * CAP_ + s) * D_);
    float4 v = src[threadIdx.x];
    v.x = to_tf32(v.x); v.y = to_tf32(v.y);
    v.z = to_tf32(v.z); v.w = to_tf32(v.w);
    dst[threadIdx.x] = v;
}

// ---------------- weight transpose: src [E,R,C] -> dst [E,C,R] (tf32-rounded) ----------------
__global__ void transpose_kernel(const float* __restrict__ src, float* __restrict__ dst,
                                 int R, int C) {
    __shared__ float t[32][33];
    int e = blockIdx.z;
    const float* S = src + (size_t)e * R * C;
    float* Dp = dst + (size_t)e * R * C;
    int c0 = blockIdx.x * 32, r0 = blockIdx.y * 32;
    int tx = threadIdx.x, ty = threadIdx.y;
#pragma unroll
    for (int j = 0; j < 4; j++)
        t[ty + 8 * j][tx] = S[(size_t)(r0 + ty + 8 * j) * C + c0 + tx];
    __syncthreads();
#pragma unroll
    for (int j = 0; j < 4; j++)
        Dp[(size_t)(c0 + ty + 8 * j) * R + r0 + tx] = to_tf32(t[tx][ty + 8 * j]);
}

// ================= unified grouped GEMM =================
// sm_103a path: tcgen05 SS tf32 + TMA 4-stage ring (warps 0-3 epilogue, 4 TMA, 5 MMA).
// fallback (plain sm_103 PTX): 256-thread mma.sync tf32 tile (R5 design) on raw pointers.

#define NSTAGES 4
#define STAGE_BYTES 16384            // 128 rows x 128B
#define SMEM_TMEM_PTR 0
#define SMEM_FULL(s) (8u + (uint32_t)(s) * 8u)
#define SMEM_EMPTY(s) (40u + (uint32_t)(s) * 8u)
#define SMEM_DONE 72u
#define SMEM_A_OFF 1024
#define SMEM_B_OFF (1024 + NSTAGES * STAGE_BYTES)
#define SMEM_TOTAL_GEMM (1024 + 2 * NSTAGES * STAGE_BYTES)   // 132096 B

#if defined(__CUDA_ARCH__) && defined(__CUDA_ARCH_FEAT_SM103_ALL)
#define HAS_TCGEN05 1
#else
#define HAS_TCGEN05 0
#endif

#if HAS_TCGEN05
#define TCGEN05_ALLOC(smem_addr, nCols) \
    asm volatile("tcgen05.alloc.cta_group::1.sync.aligned.shared::cta.b32 [%0], %1;" \
                 :: "r"((uint32_t)(smem_addr)), "r"((uint32_t)(nCols)) : "memory")
#define TCGEN05_DEALLOC(tmem_addr, nCols) \
    asm volatile("tcgen05.dealloc.cta_group::1.sync.aligned.b32 %0, %1;" \
                 :: "r"(tmem_addr), "r"((uint32_t)(nCols)))
#define TCGEN05_RELINQUISH() \
    asm volatile("tcgen05.relinquish_alloc_permit.cta_group::1.sync.aligned;")
#define TCGEN05_COMMIT(mbar) \
    asm volatile("tcgen05.commit.cta_group::1.mbarrier::arrive::one.shared::cluster.b64 [%0];" \
                 :: "r"((uint32_t)(mbar)) : "memory")
#define TCGEN05_FENCE_AFTER() \
    asm volatile("tcgen05.fence::after_thread_sync;" ::: "memory")
#define TCGEN05_FENCE_BEFORE() \
    asm volatile("tcgen05.fence::before_thread_sync;" ::: "memory")
#define TCGEN05_WAIT_LD() \
    asm volatile("tcgen05.wait::ld.sync.aligned;" ::: "memory")

#define TCGEN05_LD_32X32B_X32(r, tmem_addr) \
    asm volatile( \
        "tcgen05.ld.sync.aligned.32x32b.x32.b32 " \
        "{%0, %1, %2, %3, %4, %5, %6, %7, " \
        " %8, %9, %10, %11, %12, %13, %14, %15, " \
        " %16, %17, %18, %19, %20, %21, %22, %23, " \
        " %24, %25, %26, %27, %28, %29, %30, %31}, [%32];" \
        : "=r"((r)[0]),  "=r"((r)[1]),  "=r"((r)[2]),  "=r"((r)[3]), \
          "=r"((r)[4]),  "=r"((r)[5]),  "=r"((r)[6]),  "=r"((r)[7]), \
          "=r"((r)[8]),  "=r"((r)[9]),  "=r"((r)[10]), "=r"((r)[11]), \
          "=r"((r)[12]), "=r"((r)[13]), "=r"((r)[14]), "=r"((r)[15]), \
          "=r"((r)[16]), "=r"((r)[17]), "=r"((r)[18]), "=r"((r)[19]), \
          "=r"((r)[20]), "=r"((r)[21]), "=r"((r)[22]), "=r"((r)[23]), \
          "=r"((r)[24]), "=r"((r)[25]), "=r"((r)[26]), "=r"((r)[27]), \
          "=r"((r)[28]), "=r"((r)[29]), "=r"((r)[30]), "=r"((r)[31]) \
        : "r"(tmem_addr))

__device__ __forceinline__ void tma3d(uint32_t sdst, const CUtensorMap* tm,
                                      int cx, int cy, int cz, uint32_t mbar) {
    asm volatile(
        "cp.async.bulk.tensor.3d.shared::cta.global.tile.mbarrier::complete_tx::bytes "
        "[%0], [%1, {%2, %3, %4}], [%5];"
        :: "r"(sdst), "l"(tm), "r"(cx), "r"(cy), "r"(cz), "r"(mbar) : "memory");
}

__device__ __forceinline__ void mma_tf32_ss(uint32_t d, uint64_t ad, uint64_t bd,
                                            uint32_t idesc, uint32_t en) {
    asm volatile(
        "{\n\t.reg .pred p;\n\tsetp.ne.u32 p, %5, 0;\n\t"
        "tcgen05.mma.cta_group::1.kind::tf32 [%0], %1, %2, %3, {%4,%4,%4,%4}, p;\n\t}"
        :: "r"(d), "l"(ad), "l"(bd), "r"(idesc), "r"(0u), "r"(en) : "memory");
}

// idesc: dtype F32 | atype TF32 | btype TF32 | N=128 | M=128 (cg1)
#define MMA_IDESC ((1u << 4) | (2u << 7) | (2u << 10) | ((128u / 8u) << 17) | ((128u / 16u) << 24))
// SW128 K-major smem descriptor (version=1, LBO=1, SBO=64, layout=SW128)
#define SMEM_DESC_BASE ((2ull << 61) | (1ull << 46) | (64ull << 32) | (1ull << 16))
#define MAKE_DESC(addr) (SMEM_DESC_BASE | ((uint64_t)((addr) >> 4) & 0x3FFFull))
#endif  // HAS_TCGEN05

template <bool GELU>
__global__ __launch_bounds__(256)
void moe_gemm_tc(const __grid_constant__ CUtensorMap tmA,
                 const __grid_constant__ CUtensorMap tmB,
                 const float* __restrict__ Abase,   // fallback: A  [E,M,K] row-major
                 const float* __restrict__ Borig,   // fallback: B  [E,K,N] row-major
                 float* __restrict__ Cbase,
                 int N, int Kdim, size_t sAe, size_t sBe, size_t sCe) {
    int e = blockIdx.z;
    if ((int)blockIdx.y * 128 >= min(g_count[e], CAP_)) return;  // trim empty capacity tiles

    extern __shared__ char smem[];
    int tid = threadIdx.x;
    int wid = tid >> 5;
    int lane = tid & 31;

#if HAS_TCGEN05
    // ---------------- tcgen05 + TMA path ----------------
    uint32_t sb = smem_u32(smem);
    int kTiles = Kdim >> 5;

    if (tid == 0) {
#pragma unroll
        for (int s = 0; s < NSTAGES; s++) {
            MBARRIER_INIT(sb + SMEM_FULL(s), 1);
            MBARRIER_INIT(sb + SMEM_EMPTY(s), 1);
        }
        MBARRIER_INIT(sb + SMEM_DONE, 1);
    }
    if (wid == 5) {
        TCGEN05_ALLOC(sb + SMEM_TMEM_PTR, 128);
        TCGEN05_RELINQUISH();
    }
    __syncthreads();

    uint32_t tmem;
    asm volatile("ld.shared.b32 %0, [%1];" : "=r"(tmem) : "r"(sb + SMEM_TMEM_PTR));

    if (wid == 4) {
        // ---- TMA producer ----
        if (elect_one()) {
            int ph = 1, s = 0;
            int cy_a = blockIdx.y * 128;
            int cy_b = blockIdx.x * 128;
            for (int i = 0; i < kTiles; i++) {
                MBARRIER_WAIT_PARITY_RELAXED(sb + SMEM_EMPTY(s), ph);
                MBARRIER_EXPECT_TX(sb + SMEM_FULL(s), 2 * STAGE_BYTES);
                tma3d(sb + SMEM_A_OFF + s * STAGE_BYTES, &tmA, i * 32, cy_a, e, sb + SMEM_FULL(s));
                tma3d(sb + SMEM_B_OFF + s * STAGE_BYTES, &tmB, i * 32, cy_b, e, sb + SMEM_FULL(s));
                if (++s == NSTAGES) { s = 0; ph ^= 1; }
            }
        }
    } else if (wid == 5) {
        // ---- MMA issuer ----
        if (elect_one()) {
            uint64_t dA[NSTAGES], dB[NSTAGES];
#pragma unroll
            for (int s = 0; s < NSTAGES; s++) {
                dA[s] = MAKE_DESC(sb + SMEM_A_OFF + s * STAGE_BYTES);
                dB[s] = MAKE_DESC(sb + SMEM_B_OFF + s * STAGE_BYTES);
            }
            int ph = 0, s = 0;
            for (int i = 0; i < kTiles; i++) {
                MBARRIER_WAIT_PARITY(sb + SMEM_FULL(s), ph);
#pragma unroll
                for (int step = 0; step < 4; step++)
                    mma_tf32_ss(tmem, dA[s] + 2 * step, dB[s] + 2 * step,
                                MMA_IDESC, (i | step) != 0);
                if (i == kTiles - 1) TCGEN05_COMMIT(sb + SMEM_DONE);
                else                 TCGEN05_COMMIT(sb + SMEM_EMPTY(s));
                if (++s == NSTAGES) { s = 0; ph ^= 1; }
            }
        }
    }

    if (tid < 128) {
        // ---- epilogue: wait MMA done, read TMEM, (gelu+cvt), store ----
        MBARRIER_WAIT_PARITY(sb + SMEM_DONE, 0);
        TCGEN05_FENCE_AFTER();
        int row = blockIdx.y * 128 + wid * 32 + lane;
        float* Crow = Cbase + (size_t)e * sCe + (size_t)row * N + (size_t)blockIdx.x * 128;
#pragma unroll
        for (int c0 = 0; c0 < 128; c0 += 32) {
            uint32_t r[32];
            TCGEN05_LD_32X32B_X32(r, tmem + c0);
            TCGEN05_WAIT_LD();
#pragma unroll
            for (int j = 0; j < 32; j++) {
                float v = __uint_as_float(r[j]);
                if (GELU) { v = gelu_tanh(v); v = to_tf32(v); }
                r[j] = __float_as_uint(v);
            }
#pragma unroll
            for (int j4 = 0; j4 < 8; j4++) {
                float4 v4 = make_float4(__uint_as_float(r[4 * j4 + 0]),
                                        __uint_as_float(r[4 * j4 + 1]),
                                        __uint_as_float(r[4 * j4 + 2]),
                                        __uint_as_float(r[4 * j4 + 3]));
                *(float4*)(Crow + c0 + 4 * j4) = v4;
            }
        }
        TCGEN05_FENCE_BEFORE();
    }
    __syncthreads();
    if (wid == 5) {
        TCGEN05_DEALLOC(tmem, 128);
    }

#else
    // ---------------- fallback: mma.sync tf32 (R5 design, dynamic smem) ----------------
    (void)tmA; (void)tmB;
    float (*As)[36]  = (float(*)[36])smem;                       // 128 x 36
    float (*Bs)[132] = (float(*)[132])(smem + 128 * 36 * 4);     // 32 x 132

    const float* A = Abase + (size_t)e * sAe + (size_t)blockIdx.y * 128 * Kdim;
    const float* B = Borig + (size_t)e * sBe + (size_t)blockIdx.x * 128;
    float* C = Cbase + (size_t)e * sCe + (size_t)blockIdx.y * 128 * N + (size_t)blockIdx.x * 128;

    const int warp = wid;
    const int wm = (warp >> 2) * 64;
    const int wn = (warp & 3) * 32;
    const int r = lane >> 2;
    const int c = lane & 3;

    float acc[4][4][4];
#pragma unroll
    for (int mi = 0; mi < 4; mi++)
#pragma unroll
        for (int ni = 0; ni < 4; ni++)
#pragma unroll
            for (int q = 0; q < 4; q++) acc[mi][ni][q] = 0.f;

    for (int k0 = 0; k0 < Kdim; k0 += 32) {
#pragma unroll
        for (int it = 0; it < 4; it++) {
            int id = tid + it * 256;
            int m = id >> 3, kq = id & 7;
            float4 v = *(const float4*)(A + (size_t)m * Kdim + k0 + kq * 4);
            v.x = to_tf32(v.x); v.y = to_tf32(v.y);
            v.z = to_tf32(v.z); v.w = to_tf32(v.w);
            *(float4*)(&As[m][kq * 4]) = v;
        }
#pragma unroll
        for (int it = 0; it < 4; it++) {
            int id = tid + it * 256;
            int kk = id >> 5, n4 = id & 31;
            float4 v = *(const float4*)(B + (size_t)(k0 + kk) * N + n4 * 4);
            v.x = to_tf32(v.x); v.y = to_tf32(v.y);
            v.z = to_tf32(v.z); v.w = to_tf32(v.w);
            *(float4*)(&Bs[kk][n4 * 4]) = v;
        }
        __syncthreads();

#pragma unroll
        for (int ks = 0; ks < 4; ks++) {
            const int kb = ks * 8;
            float a[4][4];
#pragma unroll
            for (int mi = 0; mi < 4; mi++) {
                int mb = wm + mi * 16;
                a[mi][0] = As[mb + r][kb + c];
                a[mi][1] = As[mb + r + 8][kb + c];
                a[mi][2] = As[mb + r][kb + c + 4];
                a[mi][3] = As[mb + r + 8][kb + c + 4];
            }
            float b[4][2];
#pragma unroll
            for (int ni = 0; ni < 4; ni++) {
                int nb = wn + ni * 8;
                b[ni][0] = Bs[kb + c][nb + r];
                b[ni][1] = Bs[kb + c + 4][nb + r];
            }
#pragma unroll
            for (int mi = 0; mi < 4; mi++)
#pragma unroll
                for (int ni = 0; ni < 4; ni++) {
                    asm volatile(
                        "mma.sync.aligned.m16n8k8.row.col.f32.tf32.tf32.f32 "
                        "{%0,%1,%2,%3}, {%4,%5,%6,%7}, {%8,%9}, {%0,%1,%2,%3};\n"
                        : "+f"(acc[mi][ni][0]), "+f"(acc[mi][ni][1]),
                          "+f"(acc[mi][ni][2]), "+f"(acc[mi][ni][3])
                        : "r"(__float_as_uint(a[mi][0])), "r"(__float_as_uint(a[mi][1])),
                          "r"(__float_as_uint(a[mi][2])), "r"(__float_as_uint(a[mi][3])),
                          "r"(__float_as_uint(b[ni][0])), "r"(__float_as_uint(b[ni][1])));
                }
        }
        __syncthreads();
    }

#pragma unroll
    for (int mi = 0; mi < 4; mi++) {
        int row0 = wm + mi * 16 + r;
#pragma unroll
        for (int ni = 0; ni < 4; ni++) {
            int col = wn + ni * 8 + 2 * c;
            float2 v0 = make_float2(acc[mi][ni][0], acc[mi][ni][1]);
            float2 v1 = make_float2(acc[mi][ni][2], acc[mi][ni][3]);
            if (GELU) {
                v0.x = to_tf32(gelu_tanh(v0.x)); v0.y = to_tf32(gelu_tanh(v0.y));
                v1.x = to_tf32(gelu_tanh(v1.x)); v1.y = to_tf32(gelu_tanh(v1.y));
            }
            *(float2*)(C + (size_t)row0 * N + col) = v0;
            *(float2*)(C + (size_t)(row0 + 8) * N + col) = v1;
        }
    }
#endif
}

// ---------------- combine ----------------
__global__ void combine_kernel(float* __restrict__ out) {
    int t = blockIdx.x;
    float4 acc = make_float4(0.f, 0.f, 0.f, 0.f);
#pragma unroll
    for (int k = 0; k < K_; k++) {
        int a = K_ * t + k;
        int s = g_slot[a];
        if (s < CAP_) {
            float ww = g_w[a];
            int e = g_expert[a];
            float4 v = ((const float4*)(g_y + ((size_t)e * CAP_ + s) * D_))[threadIdx.x];
            acc.x += ww * v.x; acc.y += ww * v.y;
            acc.z += ww * v.z; acc.w += ww * v.w;
        }
    }
    ((float4*)(out + (size_t)t * D_))[threadIdx.x] = acc;
}

// ---------------- host: tensor map encode via runtime-resolved driver entry point ----------------
typedef CUresult (CUDAAPI *PFN_cuTensorMapEncodeTiled_v12000)(
    CUtensorMap*, CUtensorMapDataType, cuuint32_t, void*,
    const cuuint64_t*, const cuuint64_t*, const cuuint32_t*, const cuuint32_t*,
    CUtensorMapInterleave, CUtensorMapSwizzle, CUtensorMapL2promotion,
    CUtensorMapFloatOOBfill);

static PFN_cuTensorMapEncodeTiled_v12000 get_encode_fn() {
    void* fn = nullptr;
    cudaDriverEntryPointQueryResult qr = cudaDriverEntryPointSymbolNotFound;
    cudaGetDriverEntryPoint("cuTensorMapEncodeTiled", &fn, cudaEnableDefault, &qr);
    return (PFN_cuTensorMapEncodeTiled_v12000)fn;
}

static void make_tmap(PFN_cuTensorMapEncodeTiled_v12000 enc, CUtensorMap* tm,
                      void* base, uint64_t d0, uint64_t d1, uint64_t d2) {
    cuuint64_t dims[3] = {d0, d1, d2};
    cuuint64_t strides[2] = {d0 * sizeof(float), d0 * d1 * sizeof(float)};
    cuuint32_t box[3] = {32, 128, 1};
    cuuint32_t estr[3] = {1, 1, 1};
    enc(tm, CU_TENSOR_MAP_DATA_TYPE_FLOAT32, 3, base,
        dims, strides, box, estr,
        CU_TENSOR_MAP_INTERLEAVE_NONE, CU_TENSOR_MAP_SWIZZLE_128B,
        CU_TENSOR_MAP_L2_PROMOTION_L2_128B,
        CU_TENSOR_MAP_FLOAT_OOB_FILL_NONE);
}

// ---------------- launch ----------------
extern "C" void kernel_launch(void* const* d_in, const int* in_sizes, int n_in,
                              void* d_out, int out_size) {
    const float* x  = (const float*)d_in[0];   // [T, D]
    const float* Wg = (const float*)d_in[1];   // [D, E]
    const float* W1 = (const float*)d_in[2];   // [E, D, H]
    const float* W2 = (const float*)d_in[3];   // [E, H, D]
    float* out = (float*)d_out;                // [T, D]

    void *p_buf, *p_h, *p_y, *p_w1t, *p_w2t;
    cudaGetSymbolAddress(&p_buf, g_buf);
    cudaGetSymbolAddress(&p_h, g_h);
    cudaGetSymbolAddress(&p_y, g_y);
    cudaGetSymbolAddress(&p_w1t, g_w1t);
    cudaGetSymbolAddress(&p_w2t, g_w2t);

    PFN_cuTensorMapEncodeTiled_v12000 enc = get_encode_fn();
    CUtensorMap tmA1, tmB1, tmA2, tmB2;
    make_tmap(enc, &tmA1, p_buf, D_, CAP_, E_);   // A1: g_buf  [E,CAP,D]
    make_tmap(enc, &tmB1, p_w1t, D_, H_, E_);     // B1: W1^T   [E,H,D]
    make_tmap(enc, &tmA2, p_h,   H_, CAP_, E_);   // A2: g_h    [E,CAP,H]
    make_tmap(enc, &tmB2, p_w2t, H_, D_, E_);     // B2: W2^T   [E,D,H]

    cudaFuncSetAttribute(moe_gemm_tc<true>,
                         cudaFuncAttributeMaxDynamicSharedMemorySize, SMEM_TOTAL_GEMM);
    cudaFuncSetAttribute(moe_gemm_tc<false>,
                         cudaFuncAttributeMaxDynamicSharedMemorySize, SMEM_TOTAL_GEMM);

    zero_counts_kernel<<<1, 32>>>();
    router_kernel<<<T_ / 8, 256>>>(x, Wg);
    scatter_kernel<<<TK_, 256>>>(x);

    {   // W1 [E, D, H] -> g_w1t [E, H, D]
        dim3 grid(H_ / 32, D_ / 32, E_), blk(32, 8);
        transpose_kernel<<<grid, blk>>>(W1, (float*)p_w1t, D_, H_);
    }
    {   // W2 [E, H, D] -> g_w2t [E, D, H]
        dim3 grid(D_ / 32, H_ / 32, E_), blk(32, 8);
        transpose_kernel<<<grid, blk>>>(W2, (float*)p_w2t, H_, D_);
    }

    // GEMM1: h = gelu(buf @ W1)   [CAP,1024] x [1024,4096]
    {
        dim3 grid(H_ / 128, CAP_ / 128, E_);
        moe_gemm_tc<true><<<grid, 256, SMEM_TOTAL_GEMM>>>(
            tmA1, tmB1, (const float*)p_buf, W1, (float*)p_h,
            H_, D_, (size_t)CAP_ * D_, (size_t)D_ * H_, (size_t)CAP_ * H_);
    }
    // GEMM2: y = h @ W2   [CAP,4096] x [4096,1024]
    {
        dim3 grid(D_ / 128, CAP_ / 128, E_);
        moe_gemm_tc<false><<<grid, 256, SMEM_TOTAL_GEMM>>>(
            tmA2, tmB2, (const float*)p_h, W2, (float*)p_y,
            D_, H_, (size_t)CAP_ * H_, (size_t)H_ * D_, (size_t)CAP_ * D_);
    }
    combine_kernel<<<T_, 256>>>(out);
}

// round 15
// speedup vs baseline: 9.9421x; 1.1359x over previous
#include <cuda.h>
#include <cuda_runtime.h>
#include <cuda_bf16.h>
#include <math.h>
#include <stdint.h>

#define E_ 7
#define K_ 2
#define CAP_ 3072
#define D_ 1024
#define H_ 4096
#define T_ 8192
#define TK_ (T_ * K_)

// ---------------- scratch (device globals; no allocation allowed) ----------------
__device__ float g_buf[(size_t)E_ * CAP_ * D_];   // dispatched tokens  [E,CAP,D] (tf32-rounded)
__device__ float g_h  [(size_t)E_ * CAP_ * H_];   // hidden activations [E,CAP,H] (tf32-rounded)
__device__ float g_y  [(size_t)E_ * CAP_ * D_];   // expert outputs     [E,CAP,D]
__device__ float g_w1t[(size_t)E_ * H_ * D_];     // W1^T  [E,H,D] (tf32-rounded)
__device__ float g_w2t[(size_t)E_ * D_ * H_];     // W2^T  [E,D,H] (tf32-rounded)
__device__ int   g_expert[TK_];
__device__ int   g_slot[TK_];
__device__ float g_w[TK_];
__device__ int   g_count[E_];

// ---------------- common helpers ----------------
__device__ __forceinline__ float to_tf32(float x) {
    asm("cvt.rna.tf32.f32 %0, %0;" : "+f"(x));
    return x;
}
__device__ __forceinline__ float gelu_tanh(float v) {
    float c = v + 0.044715f * v * v * v;
    return 0.5f * v * (1.f + tanhf(0.7978845608028654f * c));
}
__device__ __forceinline__ uint32_t smem_u32(const void* p) {
    uint32_t a;
    asm("{ .reg .u64 t; cvta.to.shared.u64 t, %1; cvt.u32.u64 %0, t; }" : "=r"(a) : "l"(p));
    return a;
}
__device__ __forceinline__ uint32_t elect_one() {
    uint32_t p;
    asm volatile("{ .reg .pred p; elect.sync _|p, 0xFFFFFFFF; selp.b32 %0,1,0,p; }" : "=r"(p));
    return p;
}

#define MBARRIER_INIT(addr, cnt) \
    asm volatile("mbarrier.init.shared.b64 [%0], %1;" :: "r"(addr), "r"(cnt) : "memory")
#define MBARRIER_EXPECT_TX(addr, bytes) \
    asm volatile("mbarrier.arrive.expect_tx.shared.b64 _, [%0], %1;" :: "r"(addr), "r"(bytes) : "memory")

#define MBARRIER_WAIT_PARITY(mbar_, par_) do { \
    uint32_t _m = (mbar_), _p = (par_), _d; \
    asm volatile("{\n\t.reg .pred p;\n\t" \
        "mbarrier.try_wait.parity.acquire.cta.shared::cta.b64 p, [%1], %2;\n\t" \
        "selp.b32 %0, 1, 0, p;\n\t}" : "=r"(_d) : "r"(_m), "r"(_p) : "memory"); \
    if (!_d) { \
        asm volatile("{\n\t.reg .pred P1;\n\t" \
            "WL_%=:\n\t" \
            "mbarrier.try_wait.parity.acquire.cta.shared::cta.b64 P1, [%0], %1, 0x989680;\n\t" \
            "@P1 bra.uni WD_%=;\n\t" \
            "bra.uni WL_%=;\n\t" \
            "WD_%=:\n\t}" :: "r"(_m), "r"(_p) : "memory"); \
    } \
} while (0)

#define MBARRIER_WAIT_PARITY_RELAXED(mbar_, par_) do { \
    uint32_t _m = (mbar_), _p = (par_), _d; \
    asm volatile("{\n\t.reg .pred p;\n\t" \
        "mbarrier.try_wait.parity.relaxed.cta.shared::cta.b64 p, [%1], %2, 0x989680;\n\t" \
        "selp.b32 %0, 1, 0, p;\n\t}" : "=r"(_d) : "r"(_m), "r"(_p) : "memory"); \
    if (!_d) { \
        asm volatile("{\n\t.reg .pred P1;\n\t" \
            "WL_%=:\n\t" \
            "mbarrier.try_wait.parity.relaxed.cta.shared::cta.b64 P1, [%0], %1, 0x989680;\n\t" \
            "@P1 bra.uni WD_%=;\n\t" \
            "bra.uni WL_%=;\n\t" \
            "WD_%=:\n\t}" :: "r"(_m), "r"(_p) : "memory"); \
    } \
} while (0)

// ---------------- router ----------------
__global__ void zero_counts_kernel() {
    if (threadIdx.x < E_) g_count[threadIdx.x] = 0;
}

__global__ void router_kernel(const float* __restrict__ x,
                              const float* __restrict__ Wg) {
    int warp = (blockIdx.x * blockDim.x + threadIdx.x) >> 5;
    int lane = threadIdx.x & 31;
    if (warp >= T_) return;
    const float* xr = x + (size_t)warp * D_;
    float acc[E_];
#pragma unroll
    for (int e = 0; e < E_; e++) acc[e] = 0.f;
    for (int d = lane; d < D_; d += 32) {
        float xv = xr[d];
        const float* wr = Wg + (size_t)d * E_;
#pragma unroll
        for (int e = 0; e < E_; e++) acc[e] += xv * wr[e];
    }
#pragma unroll
    for (int e = 0; e < E_; e++)
#pragma unroll
        for (int o = 16; o; o >>= 1) acc[e] += __shfl_xor_sync(0xffffffffu, acc[e], o);

    if (lane == 0) {
        int i1 = 0; float l1 = acc[0];
#pragma unroll
        for (int e = 1; e < E_; e++) if (acc[e] > l1) { l1 = acc[e]; i1 = e; }
        int i2 = -1; float l2 = -3.4e38f;
#pragma unroll
        for (int e = 0; e < E_; e++) if (e != i1 && acc[e] > l2) { l2 = acc[e]; i2 = e; }
        float w2 = 1.f / (1.f + expf(l1 - l2));
        float w1 = 1.f - w2;
        int s1 = atomicAdd(&g_count[i1], 1);
        int s2 = atomicAdd(&g_count[i2], 1);
        int a = 2 * warp;
        g_expert[a] = i1; g_slot[a] = s1; g_w[a] = w1;
        g_expert[a + 1] = i2; g_slot[a + 1] = s2; g_w[a + 1] = w2;
    }
}

// ---------------- dispatch (tf32-rounds x on the way in) ----------------
__global__ void scatter_kernel(const float* __restrict__ x) {
    int a = blockIdx.x;
    int s = g_slot[a];
    if (s >= CAP_) return;
    int e = g_expert[a];
    int t = a >> 1;
    const float4* src = (const float4*)(x + (size_t)t * D_);
    float4* dst = (float4*)(g_buf + ((size_t)e * CAP_ + s) * D_);
    float4 v = src[threadIdx.x];
    v.x = to_tf32(v.x); v.y = to_tf32(v.y);
    v.z = to_tf32(v.z); v.w = to_tf32(v.w);
    dst[threadIdx.x] = v;
}

// ---------------- weight transpose: src [E,R,C] -> dst [E,C,R] (tf32-rounded) ----------------
__global__ void transpose_kernel(const float* __restrict__ src, float* __restrict__ dst,
                                 int R, int C) {
    __shared__ float t[32][33];
    int e = blockIdx.z;
    const float* S = src + (size_t)e * R * C;
    float* Dp = dst + (size_t)e * R * C;
    int c0 = blockIdx.x * 32, r0 = blockIdx.y * 32;
    int tx = threadIdx.x, ty = threadIdx.y;
#pragma unroll
    for (int j = 0; j < 4; j++)
        t[ty + 8 * j][tx] = S[(size_t)(r0 + ty + 8 * j) * C + c0 + tx];
    __syncthreads();
#pragma unroll
    for (int j = 0; j < 4; j++)
        Dp[(size_t)(c0 + ty + 8 * j) * R + r0 + tx] = to_tf32(t[tx][ty + 8 * j]);
}

// ================= unified grouped GEMM =================
// sm_103a path: tcgen05 SS tf32, BM=128 x BN=256, TMA 4-stage ring with
// B-tile multicast across a 2-CTA cluster along M (cooperative slicing).
// Warps 0-3 epilogue, warp 4 TMA producer, warp 5 MMA.
// Grid: x = M-tile (cluster pairs), y = N-tile (256 wide), z = expert.
// fallback (plain sm_103 PTX): mma.sync tf32 tile run twice per 256-col tile.

#define BN_ 256
#define NSTAGES 4
#define STAGE_A 16384                // 128 rows x 128B
#define STAGE_B 32768                // 256 rows x 128B
#define SMEM_TMEM_PTR 0
#define SMEM_FULL(s) (8u + (uint32_t)(s) * 8u)
#define SMEM_EMPTY(s) (40u + (uint32_t)(s) * 8u)
#define SMEM_DONE 72u
#define SMEM_A_OFF 1024
#define SMEM_B_OFF (1024 + NSTAGES * STAGE_A)
#define SMEM_TOTAL_GEMM (1024 + NSTAGES * (STAGE_A + STAGE_B))   // 197632 B

#if defined(__CUDA_ARCH__) && defined(__CUDA_ARCH_FEAT_SM103_ALL)
#define HAS_TCGEN05 1
#else
#define HAS_TCGEN05 0
#endif

#if HAS_TCGEN05
#define TCGEN05_ALLOC(smem_addr, nCols) \
    asm volatile("tcgen05.alloc.cta_group::1.sync.aligned.shared::cta.b32 [%0], %1;" \
                 :: "r"((uint32_t)(smem_addr)), "r"((uint32_t)(nCols)) : "memory")
#define TCGEN05_DEALLOC(tmem_addr, nCols) \
    asm volatile("tcgen05.dealloc.cta_group::1.sync.aligned.b32 %0, %1;" \
                 :: "r"(tmem_addr), "r"((uint32_t)(nCols)))
#define TCGEN05_RELINQUISH() \
    asm volatile("tcgen05.relinquish_alloc_permit.cta_group::1.sync.aligned;")
#define TCGEN05_COMMIT(mbar) \
    asm volatile("tcgen05.commit.cta_group::1.mbarrier::arrive::one.shared::cluster.b64 [%0];" \
                 :: "r"((uint32_t)(mbar)) : "memory")
#define TCGEN05_COMMIT_MCAST(mbar, mask) \
    asm volatile("tcgen05.commit.cta_group::1.mbarrier::arrive::one.shared::cluster.multicast::cluster.b64 [%0], %1;" \
                 :: "r"((uint32_t)(mbar)), "h"((uint16_t)(mask)) : "memory")
#define TCGEN05_FENCE_AFTER() \
    asm volatile("tcgen05.fence::after_thread_sync;" ::: "memory")
#define TCGEN05_FENCE_BEFORE() \
    asm volatile("tcgen05.fence::before_thread_sync;" ::: "memory")
#define TCGEN05_WAIT_LD() \
    asm volatile("tcgen05.wait::ld.sync.aligned;" ::: "memory")
#define CLUSTER_SYNC() do { \
    asm volatile("barrier.cluster.arrive.aligned;" ::: "memory"); \
    asm volatile("barrier.cluster.wait.aligned;" ::: "memory"); \
} while (0)

#define TCGEN05_LD_32X32B_X32(r, tmem_addr) \
    asm volatile( \
        "tcgen05.ld.sync.aligned.32x32b.x32.b32 " \
        "{%0, %1, %2, %3, %4, %5, %6, %7, " \
        " %8, %9, %10, %11, %12, %13, %14, %15, " \
        " %16, %17, %18, %19, %20, %21, %22, %23, " \
        " %24, %25, %26, %27, %28, %29, %30, %31}, [%32];" \
        : "=r"((r)[0]),  "=r"((r)[1]),  "=r"((r)[2]),  "=r"((r)[3]), \
          "=r"((r)[4]),  "=r"((r)[5]),  "=r"((r)[6]),  "=r"((r)[7]), \
          "=r"((r)[8]),  "=r"((r)[9]),  "=r"((r)[10]), "=r"((r)[11]), \
          "=r"((r)[12]), "=r"((r)[13]), "=r"((r)[14]), "=r"((r)[15]), \
          "=r"((r)[16]), "=r"((r)[17]), "=r"((r)[18]), "=r"((r)[19]), \
          "=r"((r)[20]), "=r"((r)[21]), "=r"((r)[22]), "=r"((r)[23]), \
          "=r"((r)[24]), "=r"((r)[25]), "=r"((r)[26]), "=r"((r)[27]), \
          "=r"((r)[28]), "=r"((r)[29]), "=r"((r)[30]), "=r"((r)[31]) \
        : "r"(tmem_addr))

__device__ __forceinline__ uint32_t cluster_rank() {
    uint32_t r;
    asm("mov.u32 %0, %%cluster_ctarank;" : "=r"(r));
    return r;
}

__device__ __forceinline__ void tma3d(uint32_t sdst, const CUtensorMap* tm,
                                      int cx, int cy, int cz, uint32_t mbar) {
    asm volatile(
        "cp.async.bulk.tensor.3d.shared::cta.global.tile.mbarrier::complete_tx::bytes "
        "[%0], [%1, {%2, %3, %4}], [%5];"
        :: "r"(sdst), "l"(tm), "r"(cx), "r"(cy), "r"(cz), "r"(mbar) : "memory");
}

__device__ __forceinline__ void tma3d_mcast(uint32_t sdst, const CUtensorMap* tm,
                                            int cx, int cy, int cz, uint32_t mbar,
                                            uint16_t mask) {
    asm volatile(
        "cp.async.bulk.tensor.3d.shared::cluster.global.tile.mbarrier::complete_tx::bytes.multicast::cluster "
        "[%0], [%1, {%2, %3, %4}], [%5], %6;"
        :: "r"(sdst), "l"(tm), "r"(cx), "r"(cy), "r"(cz), "r"(mbar), "h"(mask) : "memory");
}

__device__ __forceinline__ void mma_tf32_ss(uint32_t d, uint64_t ad, uint64_t bd,
                                            uint32_t idesc, uint32_t en) {
    asm volatile(
        "{\n\t.reg .pred p;\n\tsetp.ne.u32 p, %5, 0;\n\t"
        "tcgen05.mma.cta_group::1.kind::tf32 [%0], %1, %2, %3, {%4,%4,%4,%4}, p;\n\t}"
        :: "r"(d), "l"(ad), "l"(bd), "r"(idesc), "r"(0u), "r"(en) : "memory");
}

// idesc: dtype F32 | atype TF32 | btype TF32 | N=256 | M=128 (cg1)
#define MMA_IDESC ((1u << 4) | (2u << 7) | (2u << 10) | ((256u / 8u) << 17) | ((128u / 16u) << 24))
// SW128 K-major smem descriptor (version=1, LBO=1, SBO=64, layout=SW128)
#define SMEM_DESC_BASE ((2ull << 61) | (1ull << 46) | (64ull << 32) | (1ull << 16))
#define MAKE_DESC(addr) (SMEM_DESC_BASE | ((uint64_t)((addr) >> 4) & 0x3FFFull))
#endif  // HAS_TCGEN05

template <bool GELU>
__global__ __launch_bounds__(256)
void moe_gemm_tc(const __grid_constant__ CUtensorMap tmA,
                 const __grid_constant__ CUtensorMap tmB,
                 const float* __restrict__ Abase,   // fallback: A  [E,M,K] row-major
                 const float* __restrict__ Borig,   // fallback: B  [E,K,N] row-major
                 float* __restrict__ Cbase,
                 int N, int Kdim, size_t sAe, size_t sBe, size_t sCe) {
    int e = blockIdx.z;
    int mlim = min(g_count[e], CAP_);

    extern __shared__ char smem[];
    int tid = threadIdx.x;
    int wid = tid >> 5;
    int lane = tid & 31;

#if HAS_TCGEN05
    // ---------------- tcgen05 + TMA multicast path ----------------
    // Cluster of 2 CTAs along M sharing the 256-wide B tile.
    if ((int)(blockIdx.x & ~1u) * 128 >= mlim) return;  // whole cluster trimmed (both agree)
    bool do_store = (int)blockIdx.x * 128 < mlim;

    uint32_t sb = smem_u32(smem);
    uint32_t rank = cluster_rank();
    int kTiles = Kdim >> 5;

    if (tid == 0) {
#pragma unroll
        for (int s = 0; s < NSTAGES; s++) {
            MBARRIER_INIT(sb + SMEM_FULL(s), 1);
            MBARRIER_INIT(sb + SMEM_EMPTY(s), 2);   // one commit from each CTA's MMA
        }
        MBARRIER_INIT(sb + SMEM_DONE, 1);
    }
    if (wid == 5) {
        TCGEN05_ALLOC(sb + SMEM_TMEM_PTR, 256);
        TCGEN05_RELINQUISH();
    }
    __syncthreads();
    CLUSTER_SYNC();   // peer barriers visible before any multicast targets them

    uint32_t tmem;
    asm volatile("ld.shared.b32 %0, [%1];" : "=r"(tmem) : "r"(sb + SMEM_TMEM_PTR));

    if (wid == 4) {
        // ---- TMA producer: A local, B half multicast to both CTAs ----
        if (elect_one()) {
            int ph = 1, s = 0;
            int cy_a = blockIdx.x * 128;
            int cy_b = blockIdx.y * BN_ + rank * 128;
            for (int i = 0; i < kTiles; i++) {
                MBARRIER_WAIT_PARITY_RELAXED(sb + SMEM_EMPTY(s), ph);
                MBARRIER_EXPECT_TX(sb + SMEM_FULL(s), STAGE_A + STAGE_B);
                tma3d(sb + SMEM_A_OFF + s * STAGE_A, &tmA, i * 32, cy_a, e,
                      sb + SMEM_FULL(s));
                tma3d_mcast(sb + SMEM_B_OFF + s * STAGE_B + rank * (STAGE_B / 2),
                            &tmB, i * 32, cy_b, e, sb + SMEM_FULL(s), (uint16_t)3);
                if (++s == NSTAGES) { s = 0; ph ^= 1; }
            }
        }
    } else if (wid == 5) {
        // ---- MMA issuer ----
        if (elect_one()) {
            uint64_t dA[NSTAGES], dB[NSTAGES];
#pragma unroll
            for (int s = 0; s < NSTAGES; s++) {
                dA[s] = MAKE_DESC(sb + SMEM_A_OFF + s * STAGE_A);
                dB[s] = MAKE_DESC(sb + SMEM_B_OFF + s * STAGE_B);
            }
            int ph = 0, s = 0;
            for (int i = 0; i < kTiles; i++) {
                MBARRIER_WAIT_PARITY(sb + SMEM_FULL(s), ph);
#pragma unroll
                for (int step = 0; step < 4; step++)
                    mma_tf32_ss(tmem, dA[s] + 2 * step, dB[s] + 2 * step,
                                MMA_IDESC, (i | step) != 0);
                if (i == kTiles - 1) TCGEN05_COMMIT(sb + SMEM_DONE);
                else                 TCGEN05_COMMIT_MCAST(sb + SMEM_EMPTY(s), (uint16_t)3);
                if (++s == NSTAGES) { s = 0; ph ^= 1; }
            }
        }
    }

    if (tid < 128) {
        // ---- epilogue: wait MMA done, read TMEM, (gelu+cvt), store ----
        MBARRIER_WAIT_PARITY(sb + SMEM_DONE, 0);
        TCGEN05_FENCE_AFTER();
        int row = blockIdx.x * 128 + wid * 32 + lane;
        float* Crow = Cbase + (size_t)e * sCe + (size_t)row * N + (size_t)blockIdx.y * BN_;
#pragma unroll
        for (int c0 = 0; c0 < BN_; c0 += 32) {
            uint32_t r[32];
            TCGEN05_LD_32X32B_X32(r, tmem + c0);
            TCGEN05_WAIT_LD();
#pragma unroll
            for (int j = 0; j < 32; j++) {
                float v = __uint_as_float(r[j]);
                if (GELU) { v = gelu_tanh(v); v = to_tf32(v); }
                r[j] = __float_as_uint(v);
            }
            if (do_store) {
#pragma unroll
                for (int j4 = 0; j4 < 8; j4++) {
                    float4 v4 = make_float4(__uint_as_float(r[4 * j4 + 0]),
                                            __uint_as_float(r[4 * j4 + 1]),
                                            __uint_as_float(r[4 * j4 + 2]),
                                            __uint_as_float(r[4 * j4 + 3]));
                    *(float4*)(Crow + c0 + 4 * j4) = v4;
                }
            }
        }
        TCGEN05_FENCE_BEFORE();
    }
    __syncthreads();
    if (wid == 5) {
        TCGEN05_DEALLOC(tmem, 256);
    }
    CLUSTER_SYNC();   // no CTA exits while peer ops may target its smem

#else
    // ---------------- fallback: mma.sync tf32 (R5 tile, two 128-col halves) ----------------
    (void)tmA; (void)tmB;
    if ((int)blockIdx.x * 128 >= mlim) return;

    float (*As)[36]  = (float(*)[36])smem;                       // 128 x 36
    float (*Bs)[132] = (float(*)[132])(smem + 128 * 36 * 4);     // 32 x 132

    const int warp = wid;
    const int wm = (warp >> 2) * 64;
    const int wn = (warp & 3) * 32;
    const int r = lane >> 2;
    const int c = lane & 3;

    for (int nh = 0; nh < 2; nh++) {
        const float* A = Abase + (size_t)e * sAe + (size_t)blockIdx.x * 128 * Kdim;
        const float* B = Borig + (size_t)e * sBe + (size_t)blockIdx.y * BN_ + nh * 128;
        float* C = Cbase + (size_t)e * sCe + (size_t)blockIdx.x * 128 * N
                 + (size_t)blockIdx.y * BN_ + nh * 128;

        float acc[4][4][4];
#pragma unroll
        for (int mi = 0; mi < 4; mi++)
#pragma unroll
            for (int ni = 0; ni < 4; ni++)
#pragma unroll
                for (int q = 0; q < 4; q++) acc[mi][ni][q] = 0.f;

        for (int k0 = 0; k0 < Kdim; k0 += 32) {
#pragma unroll
            for (int it = 0; it < 4; it++) {
                int id = tid + it * 256;
                int m = id >> 3, kq = id & 7;
                float4 v = *(const float4*)(A + (size_t)m * Kdim + k0 + kq * 4);
                v.x = to_tf32(v.x); v.y = to_tf32(v.y);
                v.z = to_tf32(v.z); v.w = to_tf32(v.w);
                *(float4*)(&As[m][kq * 4]) = v;
            }
#pragma unroll
            for (int it = 0; it < 4; it++) {
                int id = tid + it * 256;
                int kk = id >> 5, n4 = id & 31;
                float4 v = *(const float4*)(B + (size_t)(k0 + kk) * N + n4 * 4);
                v.x = to_tf32(v.x); v.y = to_tf32(v.y);
                v.z = to_tf32(v.z); v.w = to_tf32(v.w);
                *(float4*)(&Bs[kk][n4 * 4]) = v;
            }
            __syncthreads();

#pragma unroll
            for (int ks = 0; ks < 4; ks++) {
                const int kb = ks * 8;
                float a[4][4];
#pragma unroll
                for (int mi = 0; mi < 4; mi++) {
                    int mb = wm + mi * 16;
                    a[mi][0] = As[mb + r][kb + c];
                    a[mi][1] = As[mb + r + 8][kb + c];
                    a[mi][2] = As[mb + r][kb + c + 4];
                    a[mi][3] = As[mb + r + 8][kb + c + 4];
                }
                float b[4][2];
#pragma unroll
                for (int ni = 0; ni < 4; ni++) {
                    int nb = wn + ni * 8;
                    b[ni][0] = Bs[kb + c][nb + r];
                    b[ni][1] = Bs[kb + c + 4][nb + r];
                }
#pragma unroll
                for (int mi = 0; mi < 4; mi++)
#pragma unroll
                    for (int ni = 0; ni < 4; ni++) {
                        asm volatile(
                            "mma.sync.aligned.m16n8k8.row.col.f32.tf32.tf32.f32 "
                            "{%0,%1,%2,%3}, {%4,%5,%6,%7}, {%8,%9}, {%0,%1,%2,%3};\n"
                            : "+f"(acc[mi][ni][0]), "+f"(acc[mi][ni][1]),
                              "+f"(acc[mi][ni][2]), "+f"(acc[mi][ni][3])
                            : "r"(__float_as_uint(a[mi][0])), "r"(__float_as_uint(a[mi][1])),
                              "r"(__float_as_uint(a[mi][2])), "r"(__float_as_uint(a[mi][3])),
                              "r"(__float_as_uint(b[ni][0])), "r"(__float_as_uint(b[ni][1])));
                    }
            }
            __syncthreads();
        }

#pragma unroll
        for (int mi = 0; mi < 4; mi++) {
            int row0 = wm + mi * 16 + r;
#pragma unroll
            for (int ni = 0; ni < 4; ni++) {
                int col = wn + ni * 8 + 2 * c;
                float2 v0 = make_float2(acc[mi][ni][0], acc[mi][ni][1]);
                float2 v1 = make_float2(acc[mi][ni][2], acc[mi][ni][3]);
                if (GELU) {
                    v0.x = to_tf32(gelu_tanh(v0.x)); v0.y = to_tf32(gelu_tanh(v0.y));
                    v1.x = to_tf32(gelu_tanh(v1.x)); v1.y = to_tf32(gelu_tanh(v1.y));
                }
                *(float2*)(C + (size_t)row0 * N + col) = v0;
                *(float2*)(C + (size_t)(row0 + 8) * N + col) = v1;
            }
        }
    }
#endif
}

// ---------------- combine ----------------
__global__ void combine_kernel(float* __restrict__ out) {
    int t = blockIdx.x;
    float4 acc = make_float4(0.f, 0.f, 0.f, 0.f);
#pragma unroll
    for (int k = 0; k < K_; k++) {
        int a = K_ * t + k;
        int s = g_slot[a];
        if (s < CAP_) {
            float ww = g_w[a];
            int e = g_expert[a];
            float4 v = ((const float4*)(g_y + ((size_t)e * CAP_ + s) * D_))[threadIdx.x];
            acc.x += ww * v.x; acc.y += ww * v.y;
            acc.z += ww * v.z; acc.w += ww * v.w;
        }
    }
    ((float4*)(out + (size_t)t * D_))[threadIdx.x] = acc;
}

// ---------------- host: tensor map encode via runtime-resolved driver entry point ----------------
typedef CUresult (CUDAAPI *PFN_cuTensorMapEncodeTiled_v12000)(
    CUtensorMap*, CUtensorMapDataType, cuuint32_t, void*,
    const cuuint64_t*, const cuuint64_t*, const cuuint32_t*, const cuuint32_t*,
    CUtensorMapInterleave, CUtensorMapSwizzle, CUtensorMapL2promotion,
    CUtensorMapFloatOOBfill);

static PFN_cuTensorMapEncodeTiled_v12000 get_encode_fn() {
    void* fn = nullptr;
    cudaDriverEntryPointQueryResult qr = cudaDriverEntryPointSymbolNotFound;
    cudaGetDriverEntryPoint("cuTensorMapEncodeTiled", &fn, cudaEnableDefault, &qr);
    return (PFN_cuTensorMapEncodeTiled_v12000)fn;
}

static void make_tmap(PFN_cuTensorMapEncodeTiled_v12000 enc, CUtensorMap* tm,
                      void* base, uint64_t d0, uint64_t d1, uint64_t d2) {
    cuuint64_t dims[3] = {d0, d1, d2};
    cuuint64_t strides[2] = {d0 * sizeof(float), d0 * d1 * sizeof(float)};
    cuuint32_t box[3] = {32, 128, 1};
    cuuint32_t estr[3] = {1, 1, 1};
    enc(tm, CU_TENSOR_MAP_DATA_TYPE_FLOAT32, 3, base,
        dims, strides, box, estr,
        CU_TENSOR_MAP_INTERLEAVE_NONE, CU_TENSOR_MAP_SWIZZLE_128B,
        CU_TENSOR_MAP_L2_PROMOTION_L2_128B,
        CU_TENSOR_MAP_FLOAT_OOB_FILL_NONE);
}

template <bool GELU>
static void launch_gemm(const CUtensorMap& tmA, const CUtensorMap& tmB,
                        const float* Abase, const float* Borig, float* Cbase,
                        int N, int Kdim, size_t sAe, size_t sBe, size_t sCe) {
    cudaLaunchConfig_t cfg = {};
    cfg.gridDim = dim3(CAP_ / 128, (unsigned)(N / BN_), E_);
    cfg.blockDim = dim3(256, 1, 1);
    cfg.dynamicSmemBytes = SMEM_TOTAL_GEMM;
    cudaLaunchAttribute attrs[1];
    attrs[0].id = cudaLaunchAttributeClusterDimension;
    attrs[0].val.clusterDim = {2, 1, 1};
    cfg.attrs = attrs;
    cfg.numAttrs = 1;
    cudaLaunchKernelEx(&cfg, moe_gemm_tc<GELU>,
                       tmA, tmB, Abase, Borig, Cbase, N, Kdim, sAe, sBe, sCe);
}

// ---------------- launch ----------------
extern "C" void kernel_launch(void* const* d_in, const int* in_sizes, int n_in,
                              void* d_out, int out_size) {
    const float* x  = (const float*)d_in[0];   // [T, D]
    const float* Wg = (const float*)d_in[1];   // [D, E]
    const float* W1 = (const float*)d_in[2];   // [E, D, H]
    const float* W2 = (const float*)d_in[3];   // [E, H, D]
    float* out = (float*)d_out;                // [T, D]

    void *p_buf, *p_h, *p_y, *p_w1t, *p_w2t;
    cudaGetSymbolAddress(&p_buf, g_buf);
    cudaGetSymbolAddress(&p_h, g_h);
    cudaGetSymbolAddress(&p_y, g_y);
    cudaGetSymbolAddress(&p_w1t, g_w1t);
    cudaGetSymbolAddress(&p_w2t, g_w2t);

    PFN_cuTensorMapEncodeTiled_v12000 enc = get_encode_fn();
    CUtensorMap tmA1, tmB1, tmA2, tmB2;
    make_tmap(enc, &tmA1, p_buf, D_, CAP_, E_);   // A1: g_buf  [E,CAP,D]
    make_tmap(enc, &tmB1, p_w1t, D_, H_, E_);     // B1: W1^T   [E,H,D]
    make_tmap(enc, &tmA2, p_h,   H_, CAP_, E_);   // A2: g_h    [E,CAP,H]
    make_tmap(enc, &tmB2, p_w2t, H_, D_, E_);     // B2: W2^T   [E,D,H]

    cudaFuncSetAttribute(moe_gemm_tc<true>,
                         cudaFuncAttributeMaxDynamicSharedMemorySize, SMEM_TOTAL_GEMM);
    cudaFuncSetAttribute(moe_gemm_tc<false>,
                         cudaFuncAttributeMaxDynamicSharedMemorySize, SMEM_TOTAL_GEMM);

    zero_counts_kernel<<<1, 32>>>();
    router_kernel<<<T_ / 8, 256>>>(x, Wg);
    scatter_kernel<<<TK_, 256>>>(x);

    {   // W1 [E, D, H] -> g_w1t [E, H, D]
        dim3 grid(H_ / 32, D_ / 32, E_), blk(32, 8);
        transpose_kernel<<<grid, blk>>>(W1, (float*)p_w1t, D_, H_);
    }
    {   // W2 [E, H, D] -> g_w2t [E, D, H]
        dim3 grid(D_ / 32, H_ / 32, E_), blk(32, 8);
        transpose_kernel<<<grid, blk>>>(W2, (float*)p_w2t, H_, D_);
    }

    // GEMM1: h = gelu(buf @ W1)   [CAP,1024] x [1024,4096]
    launch_gemm<true>(tmA1, tmB1, (const float*)p_buf, W1, (float*)p_h,
                      H_, D_, (size_t)CAP_ * D_, (size_t)D_ * H_, (size_t)CAP_ * H_);
    // GEMM2: y = h @ W2   [CAP,4096] x [4096,1024]
    launch_gemm<false>(tmA2, tmB2, (const float*)p_h, W2, (float*)p_y,
                       D_, H_, (size_t)CAP_ * H_, (size_t)H_ * D_, (size_t)CAP_ * D_);
    combine_kernel<<<T_, 256>>>(out);
}